// round 1
// baseline (speedup 1.0000x reference)
#include <cuda_runtime.h>
#include <math.h>

#define NN   50000
#define EE   640000
#define HD   128
#define NH   8
#define CC   16
#define LL   3
#define EFD  16

// ---------------- scratch (static device globals; no runtime allocation) ----
__device__ __align__(256) float    g_ea    [(size_t)EE * HD];   // edge_transform output
__device__ __align__(256) float    g_em    [(size_t)EE * HD];   // ea @ We[l]
__device__ __align__(256) float    g_xl    [(size_t)NN * HD];
__device__ __align__(256) float    g_xr    [(size_t)NN * HD];
__device__ __align__(256) float    g_logits[(size_t)EE * NH];
__device__ __align__(256) float    g_p     [(size_t)EE * NH];
__device__ __align__(256) unsigned g_lmax  [(size_t)NN * NH];
__device__ __align__(256) float    g_denom [(size_t)NN * NH];
__device__ __align__(256) float    g_agg   [(size_t)NN * HD];

// ---------------- helpers ---------------------------------------------------
__device__ __forceinline__ unsigned long long bcast2(float x) {
    unsigned long long r;
    asm("mov.b64 %0, {%1, %1};" : "=l"(r) : "f"(x));
    return r;
}
__device__ __forceinline__ void fma2(unsigned long long& acc,
                                     unsigned long long a, unsigned long long b) {
    asm("fma.rn.f32x2 %0, %1, %2, %0;" : "+l"(acc) : "l"(a), "l"(b));
}
__device__ __forceinline__ void unpack2(unsigned long long v, float& lo, float& hi) {
    asm("mov.b64 {%0, %1}, %2;" : "=f"(lo), "=f"(hi) : "l"(v));
}
__device__ __forceinline__ unsigned enc_f(float f) {
    unsigned u = __float_as_uint(f);
    return (u & 0x80000000u) ? ~u : (u | 0x80000000u);
}
__device__ __forceinline__ float dec_f(unsigned u) {
    return (u & 0x80000000u) ? __uint_as_float(u & 0x7fffffffu)
                             : __uint_as_float(~u);
}
__device__ __forceinline__ float lrelu(float x) { return fmaxf(x, 0.2f * x); }

// ---------------- kernels ---------------------------------------------------

// ea = edge_attr @ Wt + bt     ([E,16] @ [16,128])
__global__ void ea_kernel(const float* __restrict__ eattr,
                          const float* __restrict__ Wt,
                          const float* __restrict__ bt) {
    int idx = blockIdx.x * blockDim.x + threadIdx.x;
    if (idx >= EE * HD) return;
    int e = idx >> 7, j = idx & 127;
    const float* a = eattr + (size_t)e * EFD;
    float s = bt[j];
    #pragma unroll
    for (int k = 0; k < EFD; k++) s = fmaf(a[k], Wt[k * HD + j], s);
    g_ea[idx] = s;
}

// C[M,128] = A[M,128] @ W[128,128] (+ bias).  8 rows/block, f32x2 packed FMA.
__global__ void __launch_bounds__(128)
gemm128_kernel(const float* __restrict__ A, const float* __restrict__ W,
               const float* __restrict__ bias, float* __restrict__ C) {
    __shared__ float As[8][HD];
    int row0 = blockIdx.x * 8;
    for (int i = threadIdx.x; i < 8 * HD; i += 128)
        As[i >> 7][i & 127] = A[(size_t)(row0 + (i >> 7)) * HD + (i & 127)];
    __syncthreads();

    int p  = threadIdx.x & 63;     // column pair index: cols (2p, 2p+1)
    int rb = (threadIdx.x >> 6) * 4;  // rows rb..rb+3

    unsigned long long acc[4] = {0ull, 0ull, 0ull, 0ull};   // (0.f,0.f) packed
    const unsigned long long* W2 = (const unsigned long long*)W;

    #pragma unroll 16
    for (int k = 0; k < HD; k++) {
        unsigned long long w = W2[k * 64 + p];
        #pragma unroll
        for (int r = 0; r < 4; r++)
            fma2(acc[r], bcast2(As[rb + r][k]), w);
    }
    float blo = bias ? bias[2 * p]     : 0.f;
    float bhi = bias ? bias[2 * p + 1] : 0.f;
    #pragma unroll
    for (int r = 0; r < 4; r++) {
        float lo, hi; unpack2(acc[r], lo, hi);
        float2 v = make_float2(lo + blo, hi + bhi);
        *(float2*)&C[(size_t)(row0 + rb + r) * HD + 2 * p] = v;
    }
}

// zero per-layer accumulators
__global__ void zero_kernel() {
    int i = blockIdx.x * blockDim.x + threadIdx.x;
    if (i < NN * HD) g_agg[i] = 0.f;
    if (i < NN * NH) { g_denom[i] = 0.f; g_lmax[i] = 0u; }
}

// per-edge attention logits + segment max (one warp per edge)
__global__ void __launch_bounds__(256)
logits_kernel(const int* __restrict__ src, const int* __restrict__ dst,
              const float* __restrict__ att_l) {
    int e = blockIdx.x * 8 + (threadIdx.x >> 5);
    if (e >= EE) return;
    int lane = threadIdx.x & 31;
    int s = src[e], d = dst[e];
    int h = lane >> 2;

    float4 a  = *(const float4*)&g_xl[(size_t)s * HD + lane * 4];
    float4 b  = *(const float4*)&g_xr[(size_t)d * HD + lane * 4];
    float4 m  = *(const float4*)&g_em[(size_t)e * HD + lane * 4];
    float4 at = *(const float4*)&att_l[h * CC + (lane & 3) * 4];

    float sum = lrelu(a.x + b.x + m.x) * at.x
              + lrelu(a.y + b.y + m.y) * at.y
              + lrelu(a.z + b.z + m.z) * at.z
              + lrelu(a.w + b.w + m.w) * at.w;
    sum += __shfl_xor_sync(0xffffffffu, sum, 1);
    sum += __shfl_xor_sync(0xffffffffu, sum, 2);
    if ((lane & 3) == 0) {
        g_logits[(size_t)e * NH + h] = sum;
        atomicMax(&g_lmax[(size_t)d * NH + h], enc_f(sum));
    }
}

// p = exp(logit - lmax[dst]); denom[dst] += p
__global__ void softmax_kernel(const int* __restrict__ dst) {
    int i = blockIdx.x * blockDim.x + threadIdx.x;
    if (i >= EE * NH) return;
    int e = i >> 3, h = i & 7;
    int d = dst[e];
    float lm = dec_f(g_lmax[(size_t)d * NH + h]);
    float pv = expf(g_logits[i] - lm);
    g_p[i] = pv;
    atomicAdd(&g_denom[(size_t)d * NH + h], pv);
}

// agg[dst] += xl[src] * alpha   (one warp per edge, float4 red-atomics)
__global__ void __launch_bounds__(256)
aggregate_kernel(const int* __restrict__ src, const int* __restrict__ dst) {
    int e = blockIdx.x * 8 + (threadIdx.x >> 5);
    if (e >= EE) return;
    int lane = threadIdx.x & 31;
    int s = src[e], d = dst[e];
    int h = lane >> 2;
    float alpha = g_p[(size_t)e * NH + h] /
                  (g_denom[(size_t)d * NH + h] + 1e-16f);
    float4 v = *(const float4*)&g_xl[(size_t)s * HD + lane * 4];
    v.x *= alpha; v.y *= alpha; v.z *= alpha; v.w *= alpha;
    atomicAdd((float4*)&g_agg[(size_t)d * HD + lane * 4], v);
}

// x = relu(LN(agg + bias_o)) + x    (one warp per node)
__global__ void __launch_bounds__(256)
node_finish_kernel(const float* __restrict__ bo_l,
                   const float* __restrict__ lg_l,
                   const float* __restrict__ lb_l,
                   float* __restrict__ x) {
    int n = blockIdx.x * 8 + (threadIdx.x >> 5);
    if (n >= NN) return;
    int lane = threadIdx.x & 31;

    float4 v  = *(const float4*)&g_agg[(size_t)n * HD + lane * 4];
    float4 bo = *(const float4*)&bo_l[lane * 4];
    v.x += bo.x; v.y += bo.y; v.z += bo.z; v.w += bo.w;

    float s  = v.x + v.y + v.z + v.w;
    float sq = v.x * v.x + v.y * v.y + v.z * v.z + v.w * v.w;
    #pragma unroll
    for (int o = 16; o > 0; o >>= 1) {
        s  += __shfl_xor_sync(0xffffffffu, s,  o);
        sq += __shfl_xor_sync(0xffffffffu, sq, o);
    }
    float mu  = s * (1.f / HD);
    float var = sq * (1.f / HD) - mu * mu;
    float inv = rsqrtf(var + 1e-5f);

    float4 g  = *(const float4*)&lg_l[lane * 4];
    float4 bb = *(const float4*)&lb_l[lane * 4];
    float4 xi = *(const float4*)&x[(size_t)n * HD + lane * 4];

    float4 o;
    o.x = fmaxf(g.x * (v.x - mu) * inv + bb.x, 0.f) + xi.x;
    o.y = fmaxf(g.y * (v.y - mu) * inv + bb.y, 0.f) + xi.y;
    o.z = fmaxf(g.z * (v.z - mu) * inv + bb.z, 0.f) + xi.z;
    o.w = fmaxf(g.w * (v.w - mu) * inv + bb.w, 0.f) + xi.w;
    *(float4*)&x[(size_t)n * HD + lane * 4] = o;
}

// ---------------- host ------------------------------------------------------
extern "C" void kernel_launch(void* const* d_in, const int* in_sizes, int n_in,
                              void* d_out, int out_size) {
    const float* x_in   = (const float*)d_in[0];
    const int*   eidx   = (const int*)  d_in[2];
    const float* eattr  = (const float*)d_in[3];
    const float* Wt     = (const float*)d_in[4];
    const float* bt     = (const float*)d_in[5];
    const float* Wl     = (const float*)d_in[6];
    const float* bl     = (const float*)d_in[7];
    const float* Wr     = (const float*)d_in[8];
    const float* br     = (const float*)d_in[9];
    const float* We     = (const float*)d_in[10];
    const float* att    = (const float*)d_in[11];
    const float* bias_o = (const float*)d_in[12];
    const float* ln_g   = (const float*)d_in[13];
    const float* ln_b   = (const float*)d_in[14];
    float* x = (float*)d_out;

    const int* src = eidx;
    const int* dst = eidx + EE;

    float *p_ea, *p_em, *p_xl, *p_xr;
    cudaGetSymbolAddress((void**)&p_ea, g_ea);
    cudaGetSymbolAddress((void**)&p_em, g_em);
    cudaGetSymbolAddress((void**)&p_xl, g_xl);
    cudaGetSymbolAddress((void**)&p_xr, g_xr);

    // x := input x
    cudaMemcpyAsync(x, x_in, (size_t)NN * HD * sizeof(float),
                    cudaMemcpyDeviceToDevice);

    // shared edge transform
    ea_kernel<<<(EE * HD + 255) / 256, 256>>>(eattr, Wt, bt);

    for (int l = 0; l < LL; l++) {
        const float* Wl_l = Wl + (size_t)l * HD * HD;
        const float* Wr_l = Wr + (size_t)l * HD * HD;
        const float* We_l = We + (size_t)l * HD * HD;

        gemm128_kernel<<<NN / 8, 128>>>(x, Wl_l, bl + l * HD, p_xl);
        gemm128_kernel<<<NN / 8, 128>>>(x, Wr_l, br + l * HD, p_xr);
        gemm128_kernel<<<EE / 8, 128>>>(p_ea, We_l, nullptr, p_em);

        zero_kernel<<<(NN * HD + 255) / 256, 256>>>();
        logits_kernel<<<EE / 8, 256>>>(src, dst, att + l * NH * CC);
        softmax_kernel<<<(EE * NH + 255) / 256, 256>>>(dst);
        aggregate_kernel<<<EE / 8, 256>>>(src, dst);
        node_finish_kernel<<<NN / 8 + 1, 256>>>(bias_o + l * HD,
                                                ln_g + l * HD,
                                                ln_b + l * HD, x);
    }
}

// round 3
// speedup vs baseline: 1.3743x; 1.3743x over previous
#include <cuda_runtime.h>
#include <math.h>

#define NN   50000
#define EE   640000
#define HD   128
#define NH   8
#define CC   16
#define LL   3
#define EFD  16

typedef unsigned long long ull;

// ---------------- scratch (static device globals) ---------------------------
__device__ __align__(256) float g_xl   [(size_t)NN * HD];
__device__ __align__(256) float g_xr   [(size_t)NN * HD];
__device__ __align__(256) float g_p    [(size_t)EE * NH];
__device__ __align__(256) float g_denom[(size_t)NN * NH];
__device__ __align__(256) float g_agg  [(size_t)NN * HD];
__device__ __align__(256) float g_Wf   [LL][EFD * HD];   // Wt @ We[l]
__device__ __align__(256) float g_bf   [LL][HD];         // bt @ We[l]

// ---------------- helpers ---------------------------------------------------
__device__ __forceinline__ ull bcast2(float x) {
    ull r; asm("mov.b64 %0, {%1, %1};" : "=l"(r) : "f"(x)); return r;
}
__device__ __forceinline__ ull pack2(float lo, float hi) {
    ull r; asm("mov.b64 %0, {%1, %2};" : "=l"(r) : "f"(lo), "f"(hi)); return r;
}
__device__ __forceinline__ void fma2(ull& acc, ull a, ull b) {
    asm("fma.rn.f32x2 %0, %1, %2, %0;" : "+l"(acc) : "l"(a), "l"(b));
}
__device__ __forceinline__ void unpack2(ull v, float& lo, float& hi) {
    asm("mov.b64 {%0, %1}, %2;" : "=f"(lo), "=f"(hi) : "l"(v));
}
__device__ __forceinline__ float lrelu(float x) { return fmaxf(x, 0.2f * x); }

// ---------------- kernels ---------------------------------------------------

// Fold edge_transform into each layer's lin_edge:
//   Wf[l] = Wt @ We[l]  [16,128];  bf[l] = bt @ We[l]  [128]
__global__ void fusew_kernel(const float* __restrict__ Wt,
                             const float* __restrict__ bt,
                             const float* __restrict__ We) {
    int l = blockIdx.x;
    int j = threadIdx.x;                 // output column 0..127
    const float* We_l = We + (size_t)l * HD * HD;
    float b = 0.f;
    for (int m = 0; m < HD; m++) b = fmaf(bt[m], We_l[m * HD + j], b);
    g_bf[l][j] = b;
    #pragma unroll
    for (int k = 0; k < EFD; k++) {
        float s = 0.f;
        for (int m = 0; m < HD; m++) s = fmaf(Wt[k * HD + m], We_l[m * HD + j], s);
        g_Wf[l][k * HD + j] = s;
    }
}

// xl = x@Wl + bl, xr = x@Wr + br in one launch. 8 rows/block, 256 threads
// (half does Wl, half Wr). A stored transposed in smem -> 1 bcast LDS.128/k.
__global__ void __launch_bounds__(256)
node_gemm_kernel(const float* __restrict__ x,
                 const float* __restrict__ Wl_l, const float* __restrict__ bl_l,
                 const float* __restrict__ Wr_l, const float* __restrict__ br_l) {
    __shared__ float AsT[HD][8];         // [k][row]
    int row0 = blockIdx.x * 8;
    for (int i = threadIdx.x; i < 8 * HD; i += 256) {
        int r = i >> 7, c = i & 127;
        AsT[c][r] = x[(size_t)(row0 + r) * HD + c];
    }
    __syncthreads();

    int half = threadIdx.x >> 7;         // 0 -> lin_l, 1 -> lin_r
    int t    = threadIdx.x & 127;
    const float* W    = half ? Wr_l : Wl_l;
    const float* bias = half ? br_l : bl_l;
    float* C          = half ? g_xr : g_xl;

    int p  = t & 63;                     // column pair (2p, 2p+1)
    int rb = (t >> 6) * 4;               // rows rb..rb+3

    ull acc[4] = {0ull, 0ull, 0ull, 0ull};
    const ull* W2 = (const ull*)W;

    #pragma unroll 8
    for (int k = 0; k < HD; k++) {
        float4 a = *(const float4*)&AsT[k][rb];       // rows rb..rb+3 (bcast)
        ull a01 = pack2(a.x, a.y);
        ull a23 = pack2(a.z, a.w);
        ull w = W2[k * 64 + p];
        float wlo, whi; unpack2(w, wlo, whi);
        ull wl2 = bcast2(wlo), wh2 = bcast2(whi);
        fma2(acc[0], a01, wl2);  fma2(acc[1], a23, wl2);
        fma2(acc[2], a01, wh2);  fma2(acc[3], a23, wh2);
    }
    float blo = bias[2 * p], bhi = bias[2 * p + 1];
    float f0, f1;
    unpack2(acc[0], f0, f1);
    C[(size_t)(row0 + rb + 0) * HD + 2 * p] = f0 + blo;
    C[(size_t)(row0 + rb + 1) * HD + 2 * p] = f1 + blo;
    unpack2(acc[1], f0, f1);
    C[(size_t)(row0 + rb + 2) * HD + 2 * p] = f0 + blo;
    C[(size_t)(row0 + rb + 3) * HD + 2 * p] = f1 + blo;
    unpack2(acc[2], f0, f1);
    C[(size_t)(row0 + rb + 0) * HD + 2 * p + 1] = f0 + bhi;
    C[(size_t)(row0 + rb + 1) * HD + 2 * p + 1] = f1 + bhi;
    unpack2(acc[3], f0, f1);
    C[(size_t)(row0 + rb + 2) * HD + 2 * p + 1] = f0 + bhi;
    C[(size_t)(row0 + rb + 3) * HD + 2 * p + 1] = f1 + bhi;
}

// zero per-layer accumulators
__global__ void zero_kernel() {
    int i = blockIdx.x * blockDim.x + threadIdx.x;
    if (i < NN * HD) g_agg[i] = 0.f;
    if (i < NN * NH) g_denom[i] = 0.f;
}

// Fused: em on-the-fly from folded weights, logits, exp, denom atomics.
// One warp per edge, 32 edges per 1024-thread block (amortizes Wf smem load).
__global__ void __launch_bounds__(1024)
edge_p_kernel(const int* __restrict__ src, const int* __restrict__ dst,
              const float* __restrict__ eattr, const float* __restrict__ att_l,
              const float* __restrict__ Wf_l, const float* __restrict__ bf_l) {
    __shared__ float Wfs[EFD * HD];
    __shared__ float bfs[HD];
    for (int i = threadIdx.x; i < EFD * HD; i += 1024) Wfs[i] = Wf_l[i];
    if (threadIdx.x < HD) bfs[threadIdx.x] = bf_l[threadIdx.x];
    __syncthreads();

    int e = blockIdx.x * 32 + (threadIdx.x >> 5);
    if (e >= EE) return;
    int lane = threadIdx.x & 31;
    int s = src[e], d = dst[e];
    int h = lane >> 2;
    int c = lane * 4;

    // edge attrs (warp-uniform broadcast loads)
    const float4* ea4 = (const float4*)(eattr + (size_t)e * EFD);
    float4 e0 = ea4[0], e1 = ea4[1], e2 = ea4[2], e3 = ea4[3];
    float ea16[16] = {e0.x, e0.y, e0.z, e0.w, e1.x, e1.y, e1.z, e1.w,
                      e2.x, e2.y, e2.z, e2.w, e3.x, e3.y, e3.z, e3.w};

    float4 em = *(const float4*)&bfs[c];
    #pragma unroll
    for (int k = 0; k < EFD; k++) {
        float4 w = *(const float4*)&Wfs[k * HD + c];
        float a = ea16[k];
        em.x = fmaf(a, w.x, em.x); em.y = fmaf(a, w.y, em.y);
        em.z = fmaf(a, w.z, em.z); em.w = fmaf(a, w.w, em.w);
    }

    float4 a  = *(const float4*)&g_xl[(size_t)s * HD + c];
    float4 b  = *(const float4*)&g_xr[(size_t)d * HD + c];
    float4 at = *(const float4*)&att_l[h * CC + (lane & 3) * 4];

    float sum = lrelu(a.x + b.x + em.x) * at.x
              + lrelu(a.y + b.y + em.y) * at.y
              + lrelu(a.z + b.z + em.z) * at.z
              + lrelu(a.w + b.w + em.w) * at.w;
    sum += __shfl_xor_sync(0xffffffffu, sum, 1);
    sum += __shfl_xor_sync(0xffffffffu, sum, 2);
    if ((lane & 3) == 0) {
        float pv = expf(sum);               // softmax is shift-invariant
        g_p[(size_t)e * NH + h] = pv;
        atomicAdd(&g_denom[(size_t)d * NH + h], pv);
    }
}

// agg[dst] += xl[src] * p/(denom[dst]+eps)   (one warp per edge)
__global__ void __launch_bounds__(256)
aggregate_kernel(const int* __restrict__ src, const int* __restrict__ dst) {
    int e = blockIdx.x * 8 + (threadIdx.x >> 5);
    if (e >= EE) return;
    int lane = threadIdx.x & 31;
    int s = src[e], d = dst[e];
    int h = lane >> 2;
    float alpha = g_p[(size_t)e * NH + h] /
                  (g_denom[(size_t)d * NH + h] + 1e-16f);
    float4 v = *(const float4*)&g_xl[(size_t)s * HD + lane * 4];
    v.x *= alpha; v.y *= alpha; v.z *= alpha; v.w *= alpha;
    atomicAdd((float4*)&g_agg[(size_t)d * HD + lane * 4], v);
}

// x = relu(LN(agg + bias_o)) + x    (one warp per node)
__global__ void __launch_bounds__(256)
node_finish_kernel(const float* __restrict__ bo_l,
                   const float* __restrict__ lg_l,
                   const float* __restrict__ lb_l,
                   float* __restrict__ x) {
    int n = blockIdx.x * 8 + (threadIdx.x >> 5);
    if (n >= NN) return;
    int lane = threadIdx.x & 31;

    float4 v  = *(const float4*)&g_agg[(size_t)n * HD + lane * 4];
    float4 bo = *(const float4*)&bo_l[lane * 4];
    v.x += bo.x; v.y += bo.y; v.z += bo.z; v.w += bo.w;

    float s  = v.x + v.y + v.z + v.w;
    float sq = v.x * v.x + v.y * v.y + v.z * v.z + v.w * v.w;
    #pragma unroll
    for (int o = 16; o > 0; o >>= 1) {
        s  += __shfl_xor_sync(0xffffffffu, s,  o);
        sq += __shfl_xor_sync(0xffffffffu, sq, o);
    }
    float mu  = s * (1.f / HD);
    float var = sq * (1.f / HD) - mu * mu;
    float inv = rsqrtf(var + 1e-5f);

    float4 g  = *(const float4*)&lg_l[lane * 4];
    float4 bb = *(const float4*)&lb_l[lane * 4];
    float4 xi = *(const float4*)&x[(size_t)n * HD + lane * 4];

    float4 o;
    o.x = fmaxf(g.x * (v.x - mu) * inv + bb.x, 0.f) + xi.x;
    o.y = fmaxf(g.y * (v.y - mu) * inv + bb.y, 0.f) + xi.y;
    o.z = fmaxf(g.z * (v.z - mu) * inv + bb.z, 0.f) + xi.z;
    o.w = fmaxf(g.w * (v.w - mu) * inv + bb.w, 0.f) + xi.w;
    *(float4*)&x[(size_t)n * HD + lane * 4] = o;
}

// ---------------- host ------------------------------------------------------
extern "C" void kernel_launch(void* const* d_in, const int* in_sizes, int n_in,
                              void* d_out, int out_size) {
    const float* x_in   = (const float*)d_in[0];
    const int*   eidx   = (const int*)  d_in[2];
    const float* eattr  = (const float*)d_in[3];
    const float* Wt     = (const float*)d_in[4];
    const float* bt     = (const float*)d_in[5];
    const float* Wl     = (const float*)d_in[6];
    const float* bl     = (const float*)d_in[7];
    const float* Wr     = (const float*)d_in[8];
    const float* br     = (const float*)d_in[9];
    const float* We     = (const float*)d_in[10];
    const float* att    = (const float*)d_in[11];
    const float* bias_o = (const float*)d_in[12];
    const float* ln_g   = (const float*)d_in[13];
    const float* ln_b   = (const float*)d_in[14];
    float* x = (float*)d_out;

    const int* src = eidx;
    const int* dst = eidx + EE;

    float *p_Wf, *p_bf;
    cudaGetSymbolAddress((void**)&p_Wf, g_Wf);
    cudaGetSymbolAddress((void**)&p_bf, g_bf);

    cudaMemcpyAsync(x, x_in, (size_t)NN * HD * sizeof(float),
                    cudaMemcpyDeviceToDevice);

    fusew_kernel<<<LL, HD>>>(Wt, bt, We);

    for (int l = 0; l < LL; l++) {
        node_gemm_kernel<<<NN / 8, 256>>>(x,
                                          Wl + (size_t)l * HD * HD, bl + l * HD,
                                          Wr + (size_t)l * HD * HD, br + l * HD);
        zero_kernel<<<(NN * HD + 255) / 256, 256>>>();
        edge_p_kernel<<<EE / 32, 1024>>>(src, dst, eattr, att + l * NH * CC,
                                         p_Wf + (size_t)l * EFD * HD,
                                         p_bf + (size_t)l * HD);
        aggregate_kernel<<<EE / 8, 256>>>(src, dst);
        node_finish_kernel<<<NN / 8 + 1, 256>>>(bias_o + l * HD,
                                                ln_g + l * HD,
                                                ln_b + l * HD, x);
    }
}

// round 4
// speedup vs baseline: 1.9992x; 1.4546x over previous
#include <cuda_runtime.h>
#include <math.h>

#define NN   50000
#define EE   640000
#define HD   128
#define NH   8
#define CC   16
#define LL   3
#define EFD  16

typedef unsigned long long ull;

// ---------------- scratch (static device globals) ---------------------------
__device__ __align__(256) float g_xl   [(size_t)NN * HD];
__device__ __align__(256) float g_xr   [(size_t)NN * HD];
__device__ __align__(256) float g_denom[(size_t)NN * NH];
__device__ __align__(256) float g_agg  [(size_t)NN * HD];
__device__ __align__(256) float g_Wf   [LL][EFD * HD];   // Wt @ We[l]
__device__ __align__(256) float g_bf   [LL][HD];         // bt @ We[l]

// ---------------- helpers ---------------------------------------------------
__device__ __forceinline__ ull bcast2(float x) {
    ull r; asm("mov.b64 %0, {%1, %1};" : "=l"(r) : "f"(x)); return r;
}
__device__ __forceinline__ ull pack2(float lo, float hi) {
    ull r; asm("mov.b64 %0, {%1, %2};" : "=l"(r) : "f"(lo), "f"(hi)); return r;
}
__device__ __forceinline__ void fma2(ull& acc, ull a, ull b) {
    asm("fma.rn.f32x2 %0, %1, %2, %0;" : "+l"(acc) : "l"(a), "l"(b));
}
__device__ __forceinline__ void unpack2(ull v, float& lo, float& hi) {
    asm("mov.b64 {%0, %1}, %2;" : "=f"(lo), "=f"(hi) : "l"(v));
}
__device__ __forceinline__ float lrelu(float x) { return fmaxf(x, 0.2f * x); }

// ---------------- kernels ---------------------------------------------------

// Fold edge_transform into each layer's lin_edge:
//   Wf[l] = Wt @ We[l]  [16,128];  bf[l] = bt @ We[l]  [128]
__global__ void fusew_kernel(const float* __restrict__ Wt,
                             const float* __restrict__ bt,
                             const float* __restrict__ We) {
    int l = blockIdx.x;
    int j = threadIdx.x;
    const float* We_l = We + (size_t)l * HD * HD;
    float b = 0.f;
    for (int m = 0; m < HD; m++) b = fmaf(bt[m], We_l[m * HD + j], b);
    g_bf[l][j] = b;
    #pragma unroll
    for (int k = 0; k < EFD; k++) {
        float s = 0.f;
        for (int m = 0; m < HD; m++) s = fmaf(Wt[k * HD + m], We_l[m * HD + j], s);
        g_Wf[l][k * HD + j] = s;
    }
}

// xl = x@Wl + bl, xr = x@Wr + br in one launch. 8 rows/block, 256 threads.
__global__ void __launch_bounds__(256)
node_gemm_kernel(const float* __restrict__ x,
                 const float* __restrict__ Wl_l, const float* __restrict__ bl_l,
                 const float* __restrict__ Wr_l, const float* __restrict__ br_l) {
    __shared__ float AsT[HD][8];         // [k][row]
    int row0 = blockIdx.x * 8;
    for (int i = threadIdx.x; i < 8 * HD; i += 256) {
        int r = i >> 7, c = i & 127;
        AsT[c][r] = x[(size_t)(row0 + r) * HD + c];
    }
    __syncthreads();

    int half = threadIdx.x >> 7;         // 0 -> lin_l, 1 -> lin_r
    int t    = threadIdx.x & 127;
    const float* W    = half ? Wr_l : Wl_l;
    const float* bias = half ? br_l : bl_l;
    float* C          = half ? g_xr : g_xl;

    int p  = t & 63;                     // column pair (2p, 2p+1)
    int rb = (t >> 6) * 4;               // rows rb..rb+3

    ull acc[4] = {0ull, 0ull, 0ull, 0ull};
    const ull* W2 = (const ull*)W;

    #pragma unroll 8
    for (int k = 0; k < HD; k++) {
        float4 a = *(const float4*)&AsT[k][rb];
        ull a01 = pack2(a.x, a.y);
        ull a23 = pack2(a.z, a.w);
        ull w = W2[k * 64 + p];
        float wlo, whi; unpack2(w, wlo, whi);
        ull wl2 = bcast2(wlo), wh2 = bcast2(whi);
        fma2(acc[0], a01, wl2);  fma2(acc[1], a23, wl2);
        fma2(acc[2], a01, wh2);  fma2(acc[3], a23, wh2);
    }
    float blo = bias[2 * p], bhi = bias[2 * p + 1];
    float f0, f1;
    unpack2(acc[0], f0, f1);
    C[(size_t)(row0 + rb + 0) * HD + 2 * p] = f0 + blo;
    C[(size_t)(row0 + rb + 1) * HD + 2 * p] = f1 + blo;
    unpack2(acc[1], f0, f1);
    C[(size_t)(row0 + rb + 2) * HD + 2 * p] = f0 + blo;
    C[(size_t)(row0 + rb + 3) * HD + 2 * p] = f1 + blo;
    unpack2(acc[2], f0, f1);
    C[(size_t)(row0 + rb + 0) * HD + 2 * p + 1] = f0 + bhi;
    C[(size_t)(row0 + rb + 1) * HD + 2 * p + 1] = f1 + bhi;
    unpack2(acc[3], f0, f1);
    C[(size_t)(row0 + rb + 2) * HD + 2 * p + 1] = f0 + bhi;
    C[(size_t)(row0 + rb + 3) * HD + 2 * p + 1] = f1 + bhi;
}

// one-time zero of the accumulators (before layer 0)
__global__ void zero_kernel() {
    int i = blockIdx.x * blockDim.x + threadIdx.x;
    if (i < NN * HD) g_agg[i] = 0.f;
    if (i < NN * NH) g_denom[i] = 0.f;
}

// Fully fused edge pass: em (on-the-fly from folded weights) -> logit ->
// exp -> denom atomic AND unnormalized weighted scatter (p * xl[src]).
// Normalization by denom is deferred to node_finish (division distributes
// over the segment sum). One warp per edge.
__global__ void __launch_bounds__(1024)
edge_p_kernel(const int* __restrict__ src, const int* __restrict__ dst,
              const float* __restrict__ eattr, const float* __restrict__ att_l,
              const float* __restrict__ Wf_l, const float* __restrict__ bf_l) {
    __shared__ float Wfs[EFD * HD];
    __shared__ float bfs[HD];
    for (int i = threadIdx.x; i < EFD * HD; i += 1024) Wfs[i] = Wf_l[i];
    if (threadIdx.x < HD) bfs[threadIdx.x] = bf_l[threadIdx.x];
    __syncthreads();

    int e = blockIdx.x * 32 + (threadIdx.x >> 5);
    if (e >= EE) return;
    int lane = threadIdx.x & 31;
    int s = src[e], d = dst[e];
    int h = lane >> 2;
    int c = lane * 4;

    const float4* ea4 = (const float4*)(eattr + (size_t)e * EFD);
    float4 e0 = ea4[0], e1 = ea4[1], e2 = ea4[2], e3 = ea4[3];
    float ea16[16] = {e0.x, e0.y, e0.z, e0.w, e1.x, e1.y, e1.z, e1.w,
                      e2.x, e2.y, e2.z, e2.w, e3.x, e3.y, e3.z, e3.w};

    float4 em = *(const float4*)&bfs[c];
    #pragma unroll
    for (int k = 0; k < EFD; k++) {
        float4 w = *(const float4*)&Wfs[k * HD + c];
        float a = ea16[k];
        em.x = fmaf(a, w.x, em.x); em.y = fmaf(a, w.y, em.y);
        em.z = fmaf(a, w.z, em.z); em.w = fmaf(a, w.w, em.w);
    }

    float4 a  = *(const float4*)&g_xl[(size_t)s * HD + c];
    float4 b  = *(const float4*)&g_xr[(size_t)d * HD + c];
    float4 at = *(const float4*)&att_l[h * CC + (lane & 3) * 4];

    float sum = lrelu(a.x + b.x + em.x) * at.x
              + lrelu(a.y + b.y + em.y) * at.y
              + lrelu(a.z + b.z + em.z) * at.z
              + lrelu(a.w + b.w + em.w) * at.w;
    sum += __shfl_xor_sync(0xffffffffu, sum, 1);
    sum += __shfl_xor_sync(0xffffffffu, sum, 2);
    // all 4 lanes of the quad now hold the full per-head logit
    float pv = expf(sum);                   // softmax is shift-invariant
    if ((lane & 3) == 0)
        atomicAdd(&g_denom[(size_t)d * NH + h], pv);
    a.x *= pv; a.y *= pv; a.z *= pv; a.w *= pv;   // xl[src] already in regs
    atomicAdd((float4*)&g_agg[(size_t)d * HD + c], a);
}

// x = relu(LN(agg/denom + bias_o)) + x ; also re-zeroes agg/denom for the
// next layer (one warp per node).
__global__ void __launch_bounds__(256)
node_finish_kernel(const float* __restrict__ bo_l,
                   const float* __restrict__ lg_l,
                   const float* __restrict__ lb_l,
                   float* __restrict__ x) {
    int n = blockIdx.x * 8 + (threadIdx.x >> 5);
    if (n >= NN) return;
    int lane = threadIdx.x & 31;
    int h = lane >> 2;

    float den = g_denom[(size_t)n * NH + h] + 1e-16f;
    float rden = 1.f / den;

    float4 v  = *(const float4*)&g_agg[(size_t)n * HD + lane * 4];
    float4 bo = *(const float4*)&bo_l[lane * 4];
    v.x = fmaf(v.x, rden, bo.x); v.y = fmaf(v.y, rden, bo.y);
    v.z = fmaf(v.z, rden, bo.z); v.w = fmaf(v.w, rden, bo.w);

    // zero accumulators for next layer
    *(float4*)&g_agg[(size_t)n * HD + lane * 4] = make_float4(0.f, 0.f, 0.f, 0.f);
    if ((lane & 3) == 0) g_denom[(size_t)n * NH + h] = 0.f;

    float s  = v.x + v.y + v.z + v.w;
    float sq = v.x * v.x + v.y * v.y + v.z * v.z + v.w * v.w;
    #pragma unroll
    for (int o = 16; o > 0; o >>= 1) {
        s  += __shfl_xor_sync(0xffffffffu, s,  o);
        sq += __shfl_xor_sync(0xffffffffu, sq, o);
    }
    float mu  = s * (1.f / HD);
    float var = sq * (1.f / HD) - mu * mu;
    float inv = rsqrtf(var + 1e-5f);

    float4 g  = *(const float4*)&lg_l[lane * 4];
    float4 bb = *(const float4*)&lb_l[lane * 4];
    float4 xi = *(const float4*)&x[(size_t)n * HD + lane * 4];

    float4 o;
    o.x = fmaxf(g.x * (v.x - mu) * inv + bb.x, 0.f) + xi.x;
    o.y = fmaxf(g.y * (v.y - mu) * inv + bb.y, 0.f) + xi.y;
    o.z = fmaxf(g.z * (v.z - mu) * inv + bb.z, 0.f) + xi.z;
    o.w = fmaxf(g.w * (v.w - mu) * inv + bb.w, 0.f) + xi.w;
    *(float4*)&x[(size_t)n * HD + lane * 4] = o;
}

// ---------------- host ------------------------------------------------------
extern "C" void kernel_launch(void* const* d_in, const int* in_sizes, int n_in,
                              void* d_out, int out_size) {
    const float* x_in   = (const float*)d_in[0];
    const int*   eidx   = (const int*)  d_in[2];
    const float* eattr  = (const float*)d_in[3];
    const float* Wt     = (const float*)d_in[4];
    const float* bt     = (const float*)d_in[5];
    const float* Wl     = (const float*)d_in[6];
    const float* bl     = (const float*)d_in[7];
    const float* Wr     = (const float*)d_in[8];
    const float* br     = (const float*)d_in[9];
    const float* We     = (const float*)d_in[10];
    const float* att    = (const float*)d_in[11];
    const float* bias_o = (const float*)d_in[12];
    const float* ln_g   = (const float*)d_in[13];
    const float* ln_b   = (const float*)d_in[14];
    float* x = (float*)d_out;

    const int* src = eidx;
    const int* dst = eidx + EE;

    float *p_Wf, *p_bf;
    cudaGetSymbolAddress((void**)&p_Wf, g_Wf);
    cudaGetSymbolAddress((void**)&p_bf, g_bf);

    cudaMemcpyAsync(x, x_in, (size_t)NN * HD * sizeof(float),
                    cudaMemcpyDeviceToDevice);

    fusew_kernel<<<LL, HD>>>(Wt, bt, We);
    zero_kernel<<<(NN * HD + 255) / 256, 256>>>();

    for (int l = 0; l < LL; l++) {
        node_gemm_kernel<<<NN / 8, 256>>>(x,
                                          Wl + (size_t)l * HD * HD, bl + l * HD,
                                          Wr + (size_t)l * HD * HD, br + l * HD);
        edge_p_kernel<<<EE / 32, 1024>>>(src, dst, eattr, att + l * NH * CC,
                                         p_Wf + (size_t)l * EFD * HD,
                                         p_bf + (size_t)l * HD);
        node_finish_kernel<<<NN / 8 + 1, 256>>>(bias_o + l * HD,
                                                ln_g + l * HD,
                                                ln_b + l * HD, x);
    }
}